// round 2
// baseline (speedup 1.0000x reference)
#include <cuda_runtime.h>

#define B_     4096
#define HID_   1024
#define NHEADS 8

// ---- scratch (static __device__ arrays; allocation is forbidden) ----
__device__ float g_enc_h[(size_t)B_ * HID_];                  // 16 MB
__device__ float g_dec_H[(size_t)B_ * HID_];                  // 16 MB
__device__ float g_heads[(size_t)NHEADS * B_ * HID_];         // 128 MB
__device__ float g_spart[NHEADS * 8 * B_];                    // per-(head, coltile) partial scores
__device__ float g_attn[NHEADS * B_];

// ============================================================================
// Tiled SGEMM: C = relu(A[4096,K] @ B[K,1024] + bias), BM=BN=128, BK=8,
// 256 threads, 8x8 accumulators per thread, software-pipelined global loads.
// MODE 0: encoder trunk   (A = encoder_input, C = g_enc_h)
// MODE 1: decoder query   (A = decoder_input, C = g_dec_H)
// MODE 2: per-head GEMM   (A = g_enc_h, B/bias indexed by blockIdx.z,
//                          C = g_heads[k]; fused score epilogue vs g_dec_H)
// ============================================================================
template <int MODE>
__global__ __launch_bounds__(256)
void gemm_kernel(const float* __restrict__ Ain,
                 const float* __restrict__ Bin,
                 const float* __restrict__ biasin,
                 int K)
{
    const int N = HID_;
    const int kh = (MODE == 2) ? blockIdx.z : 0;

    const float* A    = (MODE == 2) ? g_enc_h : Ain;
    const float* Bm   = Bin    + (size_t)kh * K * N;
    const float* bias = biasin + (size_t)kh * N;
    float* C;
    if (MODE == 0)      C = g_enc_h;
    else if (MODE == 1) C = g_dec_H;
    else                C = g_heads + (size_t)kh * B_ * HID_;

    __shared__ float As[8][128];   // transposed A tile: As[k][m]
    __shared__ float Bs[8][128];   // Bs[k][n]

    const int tid = threadIdx.x;
    const int tr  = tid >> 4;      // 0..15, row group
    const int tc  = tid & 15;      // 0..15, col group
    const int rowTile = blockIdx.y * 128;
    const int colTile = blockIdx.x * 128;

    // global->smem load mapping (float4 per thread)
    const int aRow = tid >> 1;            // 0..127
    const int aCol = (tid & 1) * 4;       // 0 or 4
    const int bRow = tid >> 5;            // 0..7
    const int bCol = (tid & 31) * 4;      // 0..124

    const float* Aptr = A  + (size_t)(rowTile + aRow) * K + aCol;
    const float* Bptr = Bm + (size_t)bRow * N + colTile + bCol;

    float acc[8][8];
#pragma unroll
    for (int i = 0; i < 8; i++)
#pragma unroll
        for (int j = 0; j < 8; j++)
            acc[i][j] = 0.0f;

    float regM[8], regN[8];

    // ---- software pipeline: prefetch k-tile 0 ----
    float4 av = *(const float4*)Aptr;
    float4 bv = *(const float4*)Bptr;

    const int nIter = K / 8;
    for (int it = 0; it < nIter; it++) {
        // commit current fragments to smem
        As[aCol + 0][aRow] = av.x;
        As[aCol + 1][aRow] = av.y;
        As[aCol + 2][aRow] = av.z;
        As[aCol + 3][aRow] = av.w;
        *(float4*)&Bs[bRow][bCol] = bv;
        __syncthreads();

        // issue next iteration's global loads BEFORE compute (latency overlap)
        if (it + 1 < nIter) {
            Aptr += 8;
            Bptr += (size_t)8 * N;
            av = *(const float4*)Aptr;
            bv = *(const float4*)Bptr;
        }

#pragma unroll
        for (int kk = 0; kk < 8; kk++) {
#pragma unroll
            for (int i = 0; i < 8; i++) regM[i] = As[kk][tr * 8 + i];
#pragma unroll
            for (int j = 0; j < 8; j++) regN[j] = Bs[kk][tc * 8 + j];
#pragma unroll
            for (int i = 0; i < 8; i++)
#pragma unroll
                for (int j = 0; j < 8; j++)
                    acc[i][j] += regM[i] * regN[j];
        }
        __syncthreads();
    }

    // ---- epilogue: bias + relu + store (+ fused score partial for MODE 2) ----
    float bvreg[8];
    const float* bptr = bias + colTile + tc * 8;
#pragma unroll
    for (int j = 0; j < 8; j++) bvreg[j] = bptr[j];

#pragma unroll
    for (int i = 0; i < 8; i++) {
        const int r = rowTile + tr * 8 + i;
        float vals[8];
#pragma unroll
        for (int j = 0; j < 8; j++)
            vals[j] = fmaxf(acc[i][j] + bvreg[j], 0.0f);

        float4* cp = (float4*)(C + (size_t)r * HID_ + colTile + tc * 8);
        cp[0] = make_float4(vals[0], vals[1], vals[2], vals[3]);
        cp[1] = make_float4(vals[4], vals[5], vals[6], vals[7]);

        if (MODE == 2) {
            // partial score: dot(head_row_segment, dec_H_row_segment)
            const float4* dp = (const float4*)(g_dec_H + (size_t)r * HID_ + colTile + tc * 8);
            float4 d0 = dp[0], d1 = dp[1];
            float rs = vals[0]*d0.x + vals[1]*d0.y + vals[2]*d0.z + vals[3]*d0.w
                     + vals[4]*d1.x + vals[5]*d1.y + vals[6]*d1.z + vals[7]*d1.w;
            // reduce across the 16 threads (tc = 0..15) that cover this row's 128 cols
#pragma unroll
            for (int off = 8; off; off >>= 1)
                rs += __shfl_xor_sync(0xffffffffu, rs, off, 16);
            if (tc == 0)
                g_spart[(kh * 8 + blockIdx.x) * B_ + r] = rs;  // one writer: deterministic
        }
    }
}

// ============================================================================
// Softmax over heads per batch row (reduces the 8 column-tile partials first).
// ============================================================================
__global__ void softmax_kernel()
{
    const int b = blockIdx.x * blockDim.x + threadIdx.x;
    if (b >= B_) return;

    float s[NHEADS];
#pragma unroll
    for (int k = 0; k < NHEADS; k++) {
        float v = 0.0f;
#pragma unroll
        for (int j = 0; j < 8; j++)
            v += g_spart[(k * 8 + j) * B_ + b];
        s[k] = v;
    }
    float m = s[0];
#pragma unroll
    for (int k = 1; k < NHEADS; k++) m = fmaxf(m, s[k]);
    float sum = 0.0f;
#pragma unroll
    for (int k = 0; k < NHEADS; k++) { s[k] = expf(s[k] - m); sum += s[k]; }
    const float inv = 1.0f / sum;
#pragma unroll
    for (int k = 0; k < NHEADS; k++) g_attn[k * B_ + b] = s[k] * inv;
}

// ============================================================================
// contextual[b, :] = sum_k attn[k, b] * heads[k, b, :]
// one CTA per batch row; each thread owns one float4 of the 1024-dim output.
// ============================================================================
__global__ __launch_bounds__(256)
void combine_kernel(float* __restrict__ out)
{
    const int b = blockIdx.x;
    __shared__ float a[NHEADS];
    if (threadIdx.x < NHEADS) a[threadIdx.x] = g_attn[threadIdx.x * B_ + b];
    __syncthreads();

    const int d = threadIdx.x * 4;
    float4 acc = make_float4(0.f, 0.f, 0.f, 0.f);
#pragma unroll
    for (int k = 0; k < NHEADS; k++) {
        const float4 h = *(const float4*)&g_heads[((size_t)k * B_ + b) * HID_ + d];
        const float ak = a[k];
        acc.x += ak * h.x;
        acc.y += ak * h.y;
        acc.z += ak * h.z;
        acc.w += ak * h.w;
    }
    *(float4*)&out[(size_t)b * HID_ + d] = acc;
}

// ============================================================================
// launch
// ============================================================================
extern "C" void kernel_launch(void* const* d_in, const int* in_sizes, int n_in,
                              void* d_out, int out_size)
{
    const float* enc_in  = (const float*)d_in[0];  // [4096, 1024]
    const float* dec_in  = (const float*)d_in[1];  // [4096, 512]
    const float* W_enc   = (const float*)d_in[2];  // [1024, 1024]
    const float* b_enc   = (const float*)d_in[3];  // [1024]
    const float* W_heads = (const float*)d_in[4];  // [8, 1024, 1024]
    const float* b_heads = (const float*)d_in[5];  // [8, 1024]
    const float* W_dec   = (const float*)d_in[6];  // [512, 1024]
    const float* b_dec   = (const float*)d_in[7];  // [1024]
    float* out = (float*)d_out;                    // [4096, 1024]

    dim3 blk(256);
    dim3 grid(HID_ / 128, B_ / 128, 1);       // 8 x 32
    dim3 gridH(HID_ / 128, B_ / 128, NHEADS); // 8 x 32 x 8

    gemm_kernel<0><<<grid,  blk>>>(enc_in, W_enc,   b_enc,   1024);
    gemm_kernel<1><<<grid,  blk>>>(dec_in, W_dec,   b_dec,   512);
    gemm_kernel<2><<<gridH, blk>>>(nullptr, W_heads, b_heads, 1024);
    softmax_kernel<<<(B_ + 255) / 256, 256>>>();
    combine_kernel<<<B_, 256>>>(out);
}

// round 5
// speedup vs baseline: 2.8246x; 2.8246x over previous
#include <cuda_runtime.h>
#include <cuda_bf16.h>
#include <cstdint>

#define B_     4096
#define HID_   1024
#define NHEADS 8

// ============================================================================
// PTX helpers (baseline sm_80+ features only: mma.sync / ldmatrix / cp.async)
// ============================================================================
__device__ __forceinline__ uint32_t smem_to_u32(const void* p) {
    uint32_t a;
    asm("{ .reg .u64 t; cvta.to.shared.u64 t, %1; cvt.u32.u64 %0, t; }" : "=r"(a) : "l"(p));
    return a;
}
__device__ __forceinline__ void mma16816(float* c, const uint32_t* a, const uint32_t* b) {
    asm volatile("mma.sync.aligned.m16n8k16.row.col.f32.bf16.bf16.f32 "
                 "{%0,%1,%2,%3}, {%4,%5,%6,%7}, {%8,%9}, {%0,%1,%2,%3};"
                 : "+f"(c[0]), "+f"(c[1]), "+f"(c[2]), "+f"(c[3])
                 : "r"(a[0]), "r"(a[1]), "r"(a[2]), "r"(a[3]), "r"(b[0]), "r"(b[1]));
}
__device__ __forceinline__ void ldsm_x4(uint32_t* r, uint32_t addr) {
    asm volatile("ldmatrix.sync.aligned.m8n8.x4.shared.b16 {%0,%1,%2,%3}, [%4];"
                 : "=r"(r[0]), "=r"(r[1]), "=r"(r[2]), "=r"(r[3]) : "r"(addr));
}
__device__ __forceinline__ void ldsm_x2(uint32_t* r, uint32_t addr) {
    asm volatile("ldmatrix.sync.aligned.m8n8.x2.shared.b16 {%0,%1}, [%2];"
                 : "=r"(r[0]), "=r"(r[1]) : "r"(addr));
}
#define CP_ASYNC16(dst, src) \
    asm volatile("cp.async.cg.shared.global [%0], [%1], 16;" :: "r"(dst), "l"(src))
#define CP_COMMIT()  asm volatile("cp.async.commit_group;")
#define CP_WAIT_1()  asm volatile("cp.async.wait_group 1;")
#define CP_WAIT_0()  asm volatile("cp.async.wait_group 0;")

// 16B-chunk swizzle within a 64B row (4 chunks): conflict-free ldmatrix
#define SWZ(row, ch) ((ch) ^ (((row) >> 1) & 3))

// ============================================================================
// scratch (__device__ globals; allocation forbidden). 16B-aligned for cp.async.
// ============================================================================
__device__ __align__(16) __nv_bfloat16 g_encin_hi[(size_t)B_ * 1024], g_encin_lo[(size_t)B_ * 1024];
__device__ __align__(16) __nv_bfloat16 g_decin_hi[(size_t)B_ * 512],  g_decin_lo[(size_t)B_ * 512];
__device__ __align__(16) __nv_bfloat16 g_Wenc_hi[1024 * 1024],  g_Wenc_lo[1024 * 1024];   // [N,K]
__device__ __align__(16) __nv_bfloat16 g_Wdec_hi[1024 * 512],   g_Wdec_lo[1024 * 512];    // [N,K]
__device__ __align__(16) __nv_bfloat16 g_Whead_hi[(size_t)NHEADS * 1024 * 1024], g_Whead_lo[(size_t)NHEADS * 1024 * 1024];
__device__ __align__(16) __nv_bfloat16 g_ench_hi[(size_t)B_ * HID_], g_ench_lo[(size_t)B_ * HID_];
__device__ float g_dec_H[(size_t)B_ * HID_];
__device__ float g_heads[(size_t)NHEADS * B_ * HID_];
__device__ float g_spart[NHEADS * 32 * B_];      // per-(head, 32-col block) partial scores
__device__ float g_attn[NHEADS * B_];

__device__ __forceinline__ void split_bf16(float v, __nv_bfloat16& h, __nv_bfloat16& l) {
    h = __float2bfloat16(v);
    l = __float2bfloat16(v - __bfloat162float(h));
}

// ============================================================================
// activation convert: fp32 -> hi/lo bf16 planes (WHICH 0: encoder, 1: decoder)
// ============================================================================
template <int WHICH>
__global__ void convert_act(const float* __restrict__ in, int n)
{
    __nv_bfloat16* hi = (WHICH == 0) ? g_encin_hi : g_decin_hi;
    __nv_bfloat16* lo = (WHICH == 0) ? g_encin_lo : g_decin_lo;
    for (int i = blockIdx.x * blockDim.x + threadIdx.x; i < n; i += gridDim.x * blockDim.x) {
        __nv_bfloat16 h, l; split_bf16(in[i], h, l);
        hi[i] = h; lo[i] = l;
    }
}

// ============================================================================
// weight transpose+convert: fp32 [K,N] row-major -> [N,K] hi/lo bf16
// WHICH 0: W_enc (K=1024)  1: W_dec (K=512)  2: W_heads (K=1024, z=head)
// ============================================================================
template <int WHICH>
__global__ void transpose_convert(const float* __restrict__ in)
{
    const int K = (WHICH == 1) ? 512 : 1024;
    const int N = 1024;
    __nv_bfloat16* ohi = (WHICH == 0) ? g_Wenc_hi : (WHICH == 1) ? g_Wdec_hi : g_Whead_hi;
    __nv_bfloat16* olo = (WHICH == 0) ? g_Wenc_lo : (WHICH == 1) ? g_Wdec_lo : g_Whead_lo;
    const size_t moff = (size_t)blockIdx.z * K * N;
    in  += moff; ohi += moff; olo += moff;

    __shared__ float t[32][33];
    const int tx = threadIdx.x, ty = threadIdx.y;
    const int n0 = blockIdx.x * 32, k0 = blockIdx.y * 32;
#pragma unroll
    for (int j = 0; j < 32; j += 8)
        t[ty + j][tx] = in[(size_t)(k0 + ty + j) * N + n0 + tx];
    __syncthreads();
#pragma unroll
    for (int j = 0; j < 32; j += 8) {
        float v = t[tx][ty + j];                 // = in[k0+tx][n0+ty+j]
        __nv_bfloat16 h, l; split_bf16(v, h, l);
        ohi[(size_t)(n0 + ty + j) * K + k0 + tx] = h;
        olo[(size_t)(n0 + ty + j) * K + k0 + tx] = l;
    }
}

// ============================================================================
// mma.sync GEMM: 128x128 CTA tile, BK=32, 8 warps (2x4), warp tile 64x32.
// Split-precision bf16: acc += Ah*Bh + Ah*Bl + Al*Bh (fp32 accum).
// smem stage (32KB): [0] Ah[128][32] | [8K] Al | [16K] Bh[128][32] | [24K] Bl
// MODE 0: enc (K=1024) -> g_ench hi/lo   MODE 1: dec (K=512) -> g_dec_H
// MODE 2: heads (K=1024, z=head) -> g_heads + fused score partials
// ============================================================================
template <int MODE>
__global__ void __launch_bounds__(256) gemm_mma(const float* __restrict__ bias_g)
{
    constexpr int K = (MODE == 1) ? 512 : 1024;
    constexpr int nC = K / 32;
    extern __shared__ char smem[];
    const uint32_t sbase = smem_to_u32(smem);

    const int tid  = threadIdx.x;
    const int wid  = tid >> 5, lane = tid & 31;
    const int wm   = wid >> 2, wn = wid & 3;          // 2 x 4 warp grid
    const int kh   = (MODE == 2) ? blockIdx.z : 0;
    const int rowTile = blockIdx.y * 128, colTile = blockIdx.x * 128;

    const __nv_bfloat16* Ah = ((MODE == 0) ? g_encin_hi : (MODE == 1) ? g_decin_hi : g_ench_hi)
                              + (size_t)rowTile * K;
    const __nv_bfloat16* Al = ((MODE == 0) ? g_encin_lo : (MODE == 1) ? g_decin_lo : g_ench_lo)
                              + (size_t)rowTile * K;
    const __nv_bfloat16* Bh = ((MODE == 0) ? g_Wenc_hi : (MODE == 1) ? g_Wdec_hi : g_Whead_hi)
                              + (size_t)kh * 1024 * K + (size_t)colTile * K;
    const __nv_bfloat16* Bl = ((MODE == 0) ? g_Wenc_lo : (MODE == 1) ? g_Wdec_lo : g_Whead_lo)
                              + (size_t)kh * 1024 * K + (size_t)colTile * K;
    const float* bias = bias_g + ((MODE == 2) ? kh * HID_ : 0) + colTile;

    float acc[4][4][4];
#pragma unroll
    for (int i = 0; i < 4; i++)
#pragma unroll
        for (int j = 0; j < 4; j++)
#pragma unroll
            for (int e = 0; e < 4; e++) acc[i][j][e] = 0.0f;

    // ---- stage loader: 4 planes x 512 16B-chunks, 8 chunks/thread ----
    auto load_stage = [&](int s, int k0) {
        const uint32_t st = sbase + s * 32768;
#pragma unroll
        for (int p = 0; p < 4; p++) {
            const __nv_bfloat16* g = (p == 0 ? Ah : p == 1 ? Al : p == 2 ? Bh : Bl);
#pragma unroll
            for (int h = 0; h < 2; h++) {
                const int c = tid + h * 256;
                const int row = c >> 2, ch = c & 3;
                const uint32_t dst = st + p * 8192 + row * 64 + (SWZ(row, ch) << 4);
                const void* src = g + (size_t)row * K + k0 + ch * 8;
                CP_ASYNC16(dst, src);
            }
        }
        CP_COMMIT();
    };

    load_stage(0, 0);

    for (int c = 0; c < nC; c++) {
        if (c + 1 < nC) { load_stage((c + 1) & 1, (c + 1) * 32); CP_WAIT_1(); }
        else            { CP_WAIT_0(); }
        __syncthreads();

        const uint32_t st = sbase + (c & 1) * 32768;
#pragma unroll
        for (int kk = 0; kk < 2; kk++) {
            uint32_t aHf[4][4], aLf[4][4], bHf[4][2], bLf[4][2];
#pragma unroll
            for (int mt = 0; mt < 4; mt++) {
                const int row = wm * 64 + mt * 16 + (lane & 15);
                const int kc  = kk * 2 + (lane >> 4);
                const uint32_t off = row * 64 + (SWZ(row, kc) << 4);
                ldsm_x4(aHf[mt], st + off);
                ldsm_x4(aLf[mt], st + 8192 + off);
            }
#pragma unroll
            for (int nt = 0; nt < 4; nt++) {
                const int rowb = wn * 32 + nt * 8 + (lane & 7);
                const int kcb  = kk * 2 + ((lane >> 3) & 1);
                const uint32_t offb = rowb * 64 + (SWZ(rowb, kcb) << 4);
                ldsm_x2(bHf[nt], st + 16384 + offb);
                ldsm_x2(bLf[nt], st + 24576 + offb);
            }
#pragma unroll
            for (int mt = 0; mt < 4; mt++)
#pragma unroll
                for (int nt = 0; nt < 4; nt++) {
                    mma16816(acc[mt][nt], aHf[mt], bHf[nt]);
                    mma16816(acc[mt][nt], aHf[mt], bLf[nt]);
                    mma16816(acc[mt][nt], aLf[mt], bHf[nt]);
                }
        }
        __syncthreads();
    }

    // ---- epilogue: bias + relu + store (+ fused score partials, MODE 2) ----
    const int g  = lane >> 2;          // row within m16 half
    const int cq = (lane & 3) * 2;     // col pair within n8
    float2 biasv[4];
#pragma unroll
    for (int nt = 0; nt < 4; nt++)
        biasv[nt] = *(const float2*)(bias + wn * 32 + nt * 8 + cq);

#pragma unroll
    for (int mt = 0; mt < 4; mt++) {
#pragma unroll
        for (int half = 0; half < 2; half++) {
            const int r = rowTile + wm * 64 + mt * 16 + g + half * 8;
            float rs = 0.0f;
#pragma unroll
            for (int nt = 0; nt < 4; nt++) {
                const int col = colTile + wn * 32 + nt * 8 + cq;
                float v0 = fmaxf(acc[mt][nt][half * 2 + 0] + biasv[nt].x, 0.0f);
                float v1 = fmaxf(acc[mt][nt][half * 2 + 1] + biasv[nt].y, 0.0f);
                if (MODE == 0) {
                    __nv_bfloat16 h0, l0, h1, l1;
                    split_bf16(v0, h0, l0); split_bf16(v1, h1, l1);
                    *(__nv_bfloat162*)&g_ench_hi[(size_t)r * HID_ + col] = __nv_bfloat162{h0, h1};
                    *(__nv_bfloat162*)&g_ench_lo[(size_t)r * HID_ + col] = __nv_bfloat162{l0, l1};
                } else if (MODE == 1) {
                    *(float2*)&g_dec_H[(size_t)r * HID_ + col] = make_float2(v0, v1);
                } else {
                    *(float2*)&g_heads[(size_t)kh * B_ * HID_ + (size_t)r * HID_ + col] = make_float2(v0, v1);
                    const float2 dh = *(const float2*)&g_dec_H[(size_t)r * HID_ + col];
                    rs += v0 * dh.x + v1 * dh.y;
                }
            }
            if (MODE == 2) {
                rs += __shfl_xor_sync(0xffffffffu, rs, 1);
                rs += __shfl_xor_sync(0xffffffffu, rs, 2);
                if ((lane & 3) == 0)
                    g_spart[(kh * 32 + blockIdx.x * 4 + wn) * B_ + r] = rs;  // single writer
            }
        }
    }
}

// ============================================================================
// softmax over heads per batch row (sums the 32 col-block partials)
// ============================================================================
__global__ void softmax_kernel()
{
    const int b = blockIdx.x * blockDim.x + threadIdx.x;
    if (b >= B_) return;
    float s[NHEADS];
#pragma unroll
    for (int k = 0; k < NHEADS; k++) {
        float v = 0.0f;
#pragma unroll
        for (int j = 0; j < 32; j++) v += g_spart[(k * 32 + j) * B_ + b];
        s[k] = v;
    }
    float m = s[0];
#pragma unroll
    for (int k = 1; k < NHEADS; k++) m = fmaxf(m, s[k]);
    float sum = 0.0f;
#pragma unroll
    for (int k = 0; k < NHEADS; k++) { s[k] = expf(s[k] - m); sum += s[k]; }
    const float inv = 1.0f / sum;
#pragma unroll
    for (int k = 0; k < NHEADS; k++) g_attn[k * B_ + b] = s[k] * inv;
}

// ============================================================================
// contextual[b,:] = sum_k attn[k,b] * heads[k,b,:]
// ============================================================================
__global__ void __launch_bounds__(256) combine_kernel(float* __restrict__ out)
{
    const int b = blockIdx.x;
    __shared__ float a[NHEADS];
    if (threadIdx.x < NHEADS) a[threadIdx.x] = g_attn[threadIdx.x * B_ + b];
    __syncthreads();
    const int d = threadIdx.x * 4;
    float4 acc = make_float4(0.f, 0.f, 0.f, 0.f);
#pragma unroll
    for (int k = 0; k < NHEADS; k++) {
        const float4 h = *(const float4*)&g_heads[((size_t)k * B_ + b) * HID_ + d];
        const float ak = a[k];
        acc.x += ak * h.x; acc.y += ak * h.y; acc.z += ak * h.z; acc.w += ak * h.w;
    }
    *(float4*)&out[(size_t)b * HID_ + d] = acc;
}

// ============================================================================
// launch
// ============================================================================
extern "C" void kernel_launch(void* const* d_in, const int* in_sizes, int n_in,
                              void* d_out, int out_size)
{
    const float* enc_in  = (const float*)d_in[0];
    const float* dec_in  = (const float*)d_in[1];
    const float* W_enc   = (const float*)d_in[2];
    const float* b_enc   = (const float*)d_in[3];
    const float* W_heads = (const float*)d_in[4];
    const float* b_heads = (const float*)d_in[5];
    const float* W_dec   = (const float*)d_in[6];
    const float* b_dec   = (const float*)d_in[7];
    float* out = (float*)d_out;

    const int SMEM_GEMM = 2 * 32768;   // 64 KB (double-buffered stages)
    static bool attr_done = false;
    if (!attr_done) {
        cudaFuncSetAttribute(gemm_mma<0>, cudaFuncAttributeMaxDynamicSharedMemorySize, SMEM_GEMM);
        cudaFuncSetAttribute(gemm_mma<1>, cudaFuncAttributeMaxDynamicSharedMemorySize, SMEM_GEMM);
        cudaFuncSetAttribute(gemm_mma<2>, cudaFuncAttributeMaxDynamicSharedMemorySize, SMEM_GEMM);
        attr_done = true;
    }

    // converts
    convert_act<0><<<1024, 256>>>(enc_in, B_ * 1024);
    convert_act<1><<<1024, 256>>>(dec_in, B_ * 512);
    transpose_convert<0><<<dim3(32, 32, 1), dim3(32, 8)>>>(W_enc);
    transpose_convert<1><<<dim3(32, 16, 1), dim3(32, 8)>>>(W_dec);
    transpose_convert<2><<<dim3(32, 32, 8), dim3(32, 8)>>>(W_heads);

    // GEMMs (mma.sync tensor cores)
    gemm_mma<0><<<dim3(8, 32, 1), 256, SMEM_GEMM>>>(b_enc);
    gemm_mma<1><<<dim3(8, 32, 1), 256, SMEM_GEMM>>>(b_dec);
    gemm_mma<2><<<dim3(8, 32, NHEADS), 256, SMEM_GEMM>>>(b_heads);

    softmax_kernel<<<(B_ + 255) / 256, 256>>>();
    combine_kernel<<<B_, 256>>>(out);
}